// round 2
// baseline (speedup 1.0000x reference)
#include <cuda_runtime.h>
#include <math.h>

// Dimensions fixed by the problem
#define ED  172          // edge_dim
#define TD  100          // time_dim
#define DQ  356          // embed(256) + time(100)
#define DK  528          // embed(256) + edge(172) + time(100)
#define EMB 256          // embed_dim
#define TB  32           // batch rows per block

// ---- folded-weight scratch (device globals: no allocations allowed) ----
__device__ float g_cv[DQ];            // constant part of v (cos(t2v_b) rows of Wv) + bv
__device__ float g_cout[DQ];          // c_v @ Wo + bo
__device__ float g_cpre1[EMB];        // c_out @ fc1_w[0:356] + fc1_b
__device__ float g_c3[EMB];           // fc2_b @ Wsum + bsum
__device__ float g_bsum[EMB];         // lp_src_b + lp_dst_b
__device__ float g_Wsum[EMB * EMB];   // lp_src_w + lp_dst_w
__device__ float g_W2[DQ * EMB];      // Wo @ fc1_w[0:356,:]
__device__ float g_W3[EMB * EMB];     // fc2_w @ Wsum
__device__ float g_M2[ED * EMB];      // Wv[256:428,:] @ W2

// ============================================================
// Precompute stage 1: g_cv, g_Wsum, g_bsum, g_W2
// ============================================================
__global__ void __launch_bounds__(256) tgat_pre1(
    const float* __restrict__ Wv,    const float* __restrict__ bv,
    const float* __restrict__ t2v_b,
    const float* __restrict__ lps_w, const float* __restrict__ lps_b,
    const float* __restrict__ lpd_w, const float* __restrict__ lpd_b,
    const float* __restrict__ Wo,    const float* __restrict__ fc1_w)
{
    const int N_CV = DQ;
    const int N_WS = EMB * EMB;
    const int N_BS = EMB;
    const int N_W2 = DQ * EMB;
    const int total = N_CV + N_WS + N_BS + N_W2;
    for (int idx = blockIdx.x * blockDim.x + threadIdx.x; idx < total;
         idx += gridDim.x * blockDim.x) {
        if (idx < N_CV) {
            int j = idx;
            float s = bv[j];
            #pragma unroll 4
            for (int t = 0; t < TD; t++)
                s += cosf(t2v_b[t]) * Wv[(EMB + ED + t) * DQ + j];
            g_cv[j] = s;
        } else if (idx < N_CV + N_WS) {
            int i = idx - N_CV;
            g_Wsum[i] = lps_w[i] + lpd_w[i];
        } else if (idx < N_CV + N_WS + N_BS) {
            int i = idx - N_CV - N_WS;
            g_bsum[i] = lps_b[i] + lpd_b[i];
        } else {
            int i2 = idx - N_CV - N_WS - N_BS;
            int i = i2 / EMB, j = i2 % EMB;
            float s = 0.f;
            #pragma unroll 4
            for (int k = 0; k < DQ; k++)
                s += Wo[i * DQ + k] * fc1_w[k * EMB + j];
            g_W2[i2] = s;
        }
    }
}

// ============================================================
// Precompute stage 2: g_W3, g_c3, g_M2, g_cout
// (needs g_Wsum, g_bsum, g_W2, g_cv from stage 1)
// ============================================================
__global__ void __launch_bounds__(256) tgat_pre2(
    const float* __restrict__ Wv,
    const float* __restrict__ fc2_w, const float* __restrict__ fc2_b,
    const float* __restrict__ Wo,    const float* __restrict__ bo)
{
    const int N_W3 = EMB * EMB;
    const int N_C3 = EMB;
    const int N_M2 = ED * EMB;
    const int N_CO = DQ;
    const int total = N_W3 + N_C3 + N_M2 + N_CO;
    for (int idx = blockIdx.x * blockDim.x + threadIdx.x; idx < total;
         idx += gridDim.x * blockDim.x) {
        if (idx < N_W3) {
            int i = idx / EMB, j = idx % EMB;
            float s = 0.f;
            #pragma unroll 4
            for (int k = 0; k < EMB; k++)
                s += fc2_w[i * EMB + k] * g_Wsum[k * EMB + j];
            g_W3[idx] = s;
        } else if (idx < N_W3 + N_C3) {
            int j = idx - N_W3;
            float s = g_bsum[j];
            #pragma unroll 4
            for (int k = 0; k < EMB; k++)
                s += fc2_b[k] * g_Wsum[k * EMB + j];
            g_c3[j] = s;
        } else if (idx < N_W3 + N_C3 + N_M2) {
            int i2 = idx - N_W3 - N_C3;
            int e = i2 / EMB, j = i2 % EMB;
            float s = 0.f;
            #pragma unroll 4
            for (int i = 0; i < DQ; i++)
                s += Wv[(EMB + e) * DQ + i] * g_W2[i * EMB + j];
            g_M2[i2] = s;
        } else {
            int i = idx - N_W3 - N_C3 - N_M2;
            float s = bo[i];
            #pragma unroll 4
            for (int k = 0; k < DQ; k++)
                s += g_cv[k] * Wo[k * DQ + i];
            g_cout[i] = s;
        }
    }
}

// ============================================================
// Precompute stage 3: g_cpre1 = cout @ fc1_w[0:356] + fc1_b
// (FIX vs R1: multiply by fc1_w directly, NOT g_W2 — cout already
//  contains the Wo factor.)
// ============================================================
__global__ void __launch_bounds__(256) tgat_pre3(
    const float* __restrict__ fc1_w, const float* __restrict__ fc1_b)
{
    int j = threadIdx.x;
    float s = fc1_b[j];
    #pragma unroll 4
    for (int i = 0; i < DQ; i++)
        s += g_cout[i] * fc1_w[i * EMB + j];
    g_cpre1[j] = s;
}

// ============================================================
// Main fused kernel:
//   pre1 = edge @ M2 + c_pre1 ; h = relu(pre1)
//   hp   = relu(h @ W3 + c3)
//   prob = sigmoid(hp . lp_out_w + lp_out_b)
// Block: TB=32 batch rows, 256 threads (thread j = output column j).
// ============================================================
__global__ void __launch_bounds__(256) tgat_main(
    const float* __restrict__ edge,
    const float* __restrict__ lpo_w, const float* __restrict__ lpo_b,
    float* __restrict__ out, int B, int dup)
{
    __shared__ float sbuf[TB * EMB];   // 32 KB: edge tile (5504 fl) then h tile (8192 fl)
    __shared__ float red[8 * TB];

    const int tid = threadIdx.x;
    const int b0  = blockIdx.x * TB;

    // load edge tile (row-major [r][e], contiguous copy)
    for (int i = tid; i < TB * ED; i += 256)
        sbuf[i] = edge[b0 * ED + i];
    __syncthreads();

    // ---- stage 1: pre1[r][tid] = sum_e edge[r][e] * M2[e][tid] + c_pre1[tid]
    float acc[TB];
    {
        float c = g_cpre1[tid];
        #pragma unroll
        for (int r = 0; r < TB; r++) acc[r] = c;
    }
    for (int e = 0; e < ED; e++) {
        float w = g_M2[e * EMB + tid];        // coalesced, L2-resident
        #pragma unroll
        for (int r = 0; r < TB; r++)
            acc[r] = fmaf(sbuf[r * ED + e], w, acc[r]);  // smem broadcast
    }
    __syncthreads();                            // everyone done reading edge tile

    // h = relu(pre1) -> smem [r][256]
    #pragma unroll
    for (int r = 0; r < TB; r++)
        sbuf[r * EMB + tid] = fmaxf(acc[r], 0.f);
    __syncthreads();

    // ---- stage 2: hp_pre[r][tid] = sum_i h[r][i] * W3[i][tid] + c3[tid]
    {
        float c = g_c3[tid];
        #pragma unroll
        for (int r = 0; r < TB; r++) acc[r] = c;
    }
    for (int i = 0; i < EMB; i++) {
        float w = g_W3[i * EMB + tid];
        #pragma unroll
        for (int r = 0; r < TB; r++)
            acc[r] = fmaf(sbuf[r * EMB + i], w, acc[r]);
    }

    // ---- stage 3: hp = relu(hp_pre); s[r] = sum_j hp[r][j]*lpo_w[j]
    const float wl = lpo_w[tid];
    const int lane = tid & 31, warp = tid >> 5;
    #pragma unroll
    for (int r = 0; r < TB; r++) {
        float v = fmaxf(acc[r], 0.f) * wl;
        #pragma unroll
        for (int off = 16; off > 0; off >>= 1)
            v += __shfl_xor_sync(0xffffffffu, v, off);
        if (lane == 0) red[warp * TB + r] = v;
    }
    __syncthreads();

    if (tid < TB) {
        float s = lpo_b[0];
        #pragma unroll
        for (int w = 0; w < 8; w++) s += red[w * TB + tid];
        float prob = 1.f / (1.f + expf(-s));
        int b = b0 + tid;
        if (b < B) {
            out[b] = prob;                // pos_out
            if (dup) out[B + b] = prob;   // neg_out (identical)
        }
    }
}

// ============================================================
// Launch. Input order (metadata):
//  0 src(i32) 1 dst(i32) 2 time 3 edge_feats 4 t2v_w 5 t2v_b
//  6 Wq 7 bq 8 Wk 9 bk 10 Wv 11 bv 12 Wo 13 bo
//  14 fc1_w 15 fc1_b 16 fc2_w 17 fc2_b
//  18 lp_src_w 19 lp_src_b 20 lp_dst_w 21 lp_dst_b 22 lp_out_w 23 lp_out_b
// ============================================================
extern "C" void kernel_launch(void* const* d_in, const int* in_sizes, int n_in,
                              void* d_out, int out_size)
{
    const float* edge  = (const float*)d_in[3];
    const float* t2v_b = (const float*)d_in[5];
    const float* Wv    = (const float*)d_in[10];
    const float* bv    = (const float*)d_in[11];
    const float* Wo    = (const float*)d_in[12];
    const float* bo    = (const float*)d_in[13];
    const float* fc1_w = (const float*)d_in[14];
    const float* fc1_b = (const float*)d_in[15];
    const float* fc2_w = (const float*)d_in[16];
    const float* fc2_b = (const float*)d_in[17];
    const float* lps_w = (const float*)d_in[18];
    const float* lps_b = (const float*)d_in[19];
    const float* lpd_w = (const float*)d_in[20];
    const float* lpd_b = (const float*)d_in[21];
    const float* lpo_w = (const float*)d_in[22];
    const float* lpo_b = (const float*)d_in[23];

    const int B = in_sizes[0];
    float* out = (float*)d_out;
    const int dup = (out_size >= 2 * B) ? 1 : 0;

    tgat_pre1<<<592, 256>>>(Wv, bv, t2v_b, lps_w, lps_b, lpd_w, lpd_b, Wo, fc1_w);
    tgat_pre2<<<592, 256>>>(Wv, fc2_w, fc2_b, Wo, bo);
    tgat_pre3<<<1, 256>>>(fc1_w, fc1_b);
    tgat_main<<<(B + TB - 1) / TB, 256>>>(edge, lpo_w, lpo_b, out, B, dup);
}

// round 3
// speedup vs baseline: 1.4942x; 1.4942x over previous
#include <cuda_runtime.h>
#include <math.h>

// Dimensions fixed by the problem
#define ED  172          // edge_dim
#define EDP 173          // padded pitch (bank-conflict-free for 8-row stride)
#define TD  100          // time_dim
#define DQ  356          // embed(256) + time(100)
#define EMB 256          // embed_dim
#define HP  257          // padded pitch for h tile
#define TB  32           // batch rows per block

// ---- folded-weight scratch (device globals: no allocations allowed) ----
__device__ float g_cv[DQ];
__device__ float g_cout[DQ];
__device__ __align__(16) float g_cpre1[EMB];   // c_out @ fc1_w[0:356] + fc1_b
__device__ __align__(16) float g_c3[EMB];      // fc2_b @ Wsum + bsum
__device__ float g_bsum[EMB];
__device__ float g_Wsum[EMB * EMB];            // lp_src_w + lp_dst_w
__device__ float g_W2[DQ * EMB];               // Wo @ fc1_w[0:356,:]
__device__ __align__(16) float g_W3[EMB * EMB]; // fc2_w @ Wsum
__device__ __align__(16) float g_M2[ED * EMB];  // Wv[256:428,:] @ W2

// ============================================================
// Precompute stage 1: g_cv, g_Wsum, g_bsum, g_W2
// ============================================================
__global__ void __launch_bounds__(256) tgat_pre1(
    const float* __restrict__ Wv,    const float* __restrict__ bv,
    const float* __restrict__ t2v_b,
    const float* __restrict__ lps_w, const float* __restrict__ lps_b,
    const float* __restrict__ lpd_w, const float* __restrict__ lpd_b,
    const float* __restrict__ Wo,    const float* __restrict__ fc1_w)
{
    const int N_CV = DQ;
    const int N_WS = EMB * EMB;
    const int N_BS = EMB;
    const int N_W2 = DQ * EMB;
    const int total = N_CV + N_WS + N_BS + N_W2;
    for (int idx = blockIdx.x * blockDim.x + threadIdx.x; idx < total;
         idx += gridDim.x * blockDim.x) {
        if (idx < N_CV) {
            int j = idx;
            float s = bv[j];
            #pragma unroll 4
            for (int t = 0; t < TD; t++)
                s += cosf(t2v_b[t]) * Wv[(EMB + ED + t) * DQ + j];
            g_cv[j] = s;
        } else if (idx < N_CV + N_WS) {
            int i = idx - N_CV;
            g_Wsum[i] = lps_w[i] + lpd_w[i];
        } else if (idx < N_CV + N_WS + N_BS) {
            int i = idx - N_CV - N_WS;
            g_bsum[i] = lps_b[i] + lpd_b[i];
        } else {
            int i2 = idx - N_CV - N_WS - N_BS;
            int i = i2 / EMB, j = i2 % EMB;
            float s = 0.f;
            #pragma unroll 4
            for (int k = 0; k < DQ; k++)
                s += Wo[i * DQ + k] * fc1_w[k * EMB + j];
            g_W2[i2] = s;
        }
    }
}

// ============================================================
// Precompute stage 2: g_W3, g_c3, g_M2, g_cout
// ============================================================
__global__ void __launch_bounds__(256) tgat_pre2(
    const float* __restrict__ Wv,
    const float* __restrict__ fc2_w, const float* __restrict__ fc2_b,
    const float* __restrict__ Wo,    const float* __restrict__ bo)
{
    const int N_W3 = EMB * EMB;
    const int N_C3 = EMB;
    const int N_M2 = ED * EMB;
    const int N_CO = DQ;
    const int total = N_W3 + N_C3 + N_M2 + N_CO;
    for (int idx = blockIdx.x * blockDim.x + threadIdx.x; idx < total;
         idx += gridDim.x * blockDim.x) {
        if (idx < N_W3) {
            int i = idx / EMB, j = idx % EMB;
            float s = 0.f;
            #pragma unroll 4
            for (int k = 0; k < EMB; k++)
                s += fc2_w[i * EMB + k] * g_Wsum[k * EMB + j];
            g_W3[idx] = s;
        } else if (idx < N_W3 + N_C3) {
            int j = idx - N_W3;
            float s = g_bsum[j];
            #pragma unroll 4
            for (int k = 0; k < EMB; k++)
                s += fc2_b[k] * g_Wsum[k * EMB + j];
            g_c3[j] = s;
        } else if (idx < N_W3 + N_C3 + N_M2) {
            int i2 = idx - N_W3 - N_C3;
            int e = i2 / EMB, j = i2 % EMB;
            float s = 0.f;
            #pragma unroll 4
            for (int i = 0; i < DQ; i++)
                s += Wv[(EMB + e) * DQ + i] * g_W2[i * EMB + j];
            g_M2[i2] = s;
        } else {
            int i = idx - N_W3 - N_C3 - N_M2;
            float s = bo[i];
            #pragma unroll 4
            for (int k = 0; k < DQ; k++)
                s += g_cv[k] * Wo[k * DQ + i];
            g_cout[i] = s;
        }
    }
}

// ============================================================
// Precompute stage 3: g_cpre1 = cout @ fc1_w[0:356] + fc1_b
// ============================================================
__global__ void __launch_bounds__(256) tgat_pre3(
    const float* __restrict__ fc1_w, const float* __restrict__ fc1_b)
{
    int j = threadIdx.x;
    float s = fc1_b[j];
    #pragma unroll 4
    for (int i = 0; i < DQ; i++)
        s += g_cout[i] * fc1_w[i * EMB + j];
    g_cpre1[j] = s;
}

// ============================================================
// Main fused kernel, 2-D register tiled.
//   Block: 32 batch rows, 256 threads = 8 warps.
//   Warp w owns col slice [w*32, w*32+32).
//   Thread: rows r0..r0+7 (r0 = (lane>>3)*8), cols c0..c0+3 (c0 = w*32+(lane&7)*4).
//   Stage1: pre1 = edge @ M2 + c_pre1 ; h = relu(pre1) -> smem
//   Stage2: hp   = relu(h @ W3 + c3)
//   Stage3: prob = sigmoid(hp . lp_out_w + lp_out_b)
// ============================================================
__global__ void __launch_bounds__(256, 2) tgat_main(
    const float* __restrict__ edge,
    const float* __restrict__ lpo_w, const float* __restrict__ lpo_b,
    float* __restrict__ out, int B, int dup)
{
    __shared__ float sbuf[TB * HP];    // 32.9 KB; edge tile (32x173) then h tile (32x257)
    __shared__ float red[8 * TB];      // per-warp partial row sums

    const int tid  = threadIdx.x;
    const int lane = tid & 31;
    const int w    = tid >> 5;
    const int lm8  = lane & 7;
    const int r0   = (lane >> 3) * 8;
    const int c0   = w * 32 + lm8 * 4;
    const int widx = c0 >> 2;          // float4 index within a weight row
    const int b0   = blockIdx.x * TB;

    // ---- load edge tile [32][172] -> sbuf pitch 173 ----
    for (int i = tid; i < TB * ED; i += 256) {
        int r = i / ED, e = i - r * ED;
        sbuf[r * EDP + e] = edge[b0 * ED + i];
    }
    __syncthreads();

    // ---- stage 1: acc[i][j] = sum_e edge[r0+i][e] * M2[e][c0+j] + cpre1 ----
    float acc[8][4];
    {
        float4 cp = *(const float4*)(g_cpre1 + c0);
        #pragma unroll
        for (int i = 0; i < 8; i++) {
            acc[i][0] = cp.x; acc[i][1] = cp.y; acc[i][2] = cp.z; acc[i][3] = cp.w;
        }
    }
    {
        const float4* M2v = (const float4*)g_M2;
        const float*  pe  = sbuf + r0 * EDP;
        #pragma unroll 2
        for (int e = 0; e < ED; e++) {
            float4 wv = M2v[e * (EMB / 4) + widx];
            float a[8];
            #pragma unroll
            for (int i = 0; i < 8; i++) a[i] = pe[i * EDP + e];
            #pragma unroll
            for (int i = 0; i < 8; i++) {
                acc[i][0] = fmaf(a[i], wv.x, acc[i][0]);
                acc[i][1] = fmaf(a[i], wv.y, acc[i][1]);
                acc[i][2] = fmaf(a[i], wv.z, acc[i][2]);
                acc[i][3] = fmaf(a[i], wv.w, acc[i][3]);
            }
        }
    }
    __syncthreads();   // everyone done reading the edge tile

    // ---- h = relu(pre1) -> sbuf pitch 257 (overlays edge tile) ----
    #pragma unroll
    for (int i = 0; i < 8; i++) {
        #pragma unroll
        for (int j = 0; j < 4; j++)
            sbuf[(r0 + i) * HP + c0 + j] = fmaxf(acc[i][j], 0.f);
    }
    __syncthreads();

    // ---- stage 2: acc[i][j] = sum_k h[r0+i][k] * W3[k][c0+j] + c3 ----
    {
        float4 cc = *(const float4*)(g_c3 + c0);
        #pragma unroll
        for (int i = 0; i < 8; i++) {
            acc[i][0] = cc.x; acc[i][1] = cc.y; acc[i][2] = cc.z; acc[i][3] = cc.w;
        }
    }
    {
        const float4* W3v = (const float4*)g_W3;
        const float*  ph  = sbuf + r0 * HP;
        #pragma unroll 2
        for (int k = 0; k < EMB; k++) {
            float4 wv = W3v[k * (EMB / 4) + widx];
            float a[8];
            #pragma unroll
            for (int i = 0; i < 8; i++) a[i] = ph[i * HP + k];
            #pragma unroll
            for (int i = 0; i < 8; i++) {
                acc[i][0] = fmaf(a[i], wv.x, acc[i][0]);
                acc[i][1] = fmaf(a[i], wv.y, acc[i][1]);
                acc[i][2] = fmaf(a[i], wv.z, acc[i][2]);
                acc[i][3] = fmaf(a[i], wv.w, acc[i][3]);
            }
        }
    }

    // ---- stage 3: hp = relu(acc); per-row dot with lpo_w ----
    {
        float4 wl = *(const float4*)(lpo_w + c0);
        float part[8];
        #pragma unroll
        for (int i = 0; i < 8; i++) {
            part[i] = fmaxf(acc[i][0], 0.f) * wl.x
                    + fmaxf(acc[i][1], 0.f) * wl.y
                    + fmaxf(acc[i][2], 0.f) * wl.z
                    + fmaxf(acc[i][3], 0.f) * wl.w;
        }
        // reduce across the 8 col-subgroups (low 3 lane bits)
        #pragma unroll
        for (int off = 1; off < 8; off <<= 1) {
            #pragma unroll
            for (int i = 0; i < 8; i++)
                part[i] += __shfl_xor_sync(0xffffffffu, part[i], off);
        }
        if (lm8 == 0) {
            #pragma unroll
            for (int i = 0; i < 8; i++)
                red[w * TB + r0 + i] = part[i];   // warp w's col-slice sum for row r0+i
        }
    }
    __syncthreads();

    if (tid < TB) {
        float s = lpo_b[0];
        #pragma unroll
        for (int ww = 0; ww < 8; ww++) s += red[ww * TB + tid];
        float prob = 1.f / (1.f + expf(-s));
        int b = b0 + tid;
        if (b < B) {
            out[b] = prob;                // pos_out
            if (dup) out[B + b] = prob;   // neg_out (identical)
        }
    }
}

// ============================================================
// Launch. Input order (metadata):
//  0 src(i32) 1 dst(i32) 2 time 3 edge_feats 4 t2v_w 5 t2v_b
//  6 Wq 7 bq 8 Wk 9 bk 10 Wv 11 bv 12 Wo 13 bo
//  14 fc1_w 15 fc1_b 16 fc2_w 17 fc2_b
//  18 lp_src_w 19 lp_src_b 20 lp_dst_w 21 lp_dst_b 22 lp_out_w 23 lp_out_b
// ============================================================
extern "C" void kernel_launch(void* const* d_in, const int* in_sizes, int n_in,
                              void* d_out, int out_size)
{
    const float* edge  = (const float*)d_in[3];
    const float* t2v_b = (const float*)d_in[5];
    const float* Wv    = (const float*)d_in[10];
    const float* bv    = (const float*)d_in[11];
    const float* Wo    = (const float*)d_in[12];
    const float* bo    = (const float*)d_in[13];
    const float* fc1_w = (const float*)d_in[14];
    const float* fc1_b = (const float*)d_in[15];
    const float* fc2_w = (const float*)d_in[16];
    const float* fc2_b = (const float*)d_in[17];
    const float* lps_w = (const float*)d_in[18];
    const float* lps_b = (const float*)d_in[19];
    const float* lpd_w = (const float*)d_in[20];
    const float* lpd_b = (const float*)d_in[21];
    const float* lpo_w = (const float*)d_in[22];
    const float* lpo_b = (const float*)d_in[23];

    const int B = in_sizes[0];
    float* out = (float*)d_out;
    const int dup = (out_size >= 2 * B) ? 1 : 0;

    tgat_pre1<<<592, 256>>>(Wv, bv, t2v_b, lps_w, lps_b, lpd_w, lpd_b, Wo, fc1_w);
    tgat_pre2<<<592, 256>>>(Wv, fc2_w, fc2_b, Wo, bo);
    tgat_pre3<<<1, 256>>>(fc1_w, fc1_b);
    tgat_main<<<(B + TB - 1) / TB, 256>>>(edge, lpo_w, lpo_b, out, B, dup);
}